// round 5
// baseline (speedup 1.0000x reference)
#include <cuda_runtime.h>
#include <math.h>

#define BATCH 4
#define NTOK  2048
#define DMODEL 1024
#define HEADS 16
#define DH    64
#define INNER 1024
#define SCALE 0.125f   /* 64^-0.5 */

typedef unsigned long long u64;

__device__ __forceinline__ u64 pack2(float x) {
    u64 r; asm("mov.b64 %0, {%1, %1};" : "=l"(r) : "f"(x)); return r;
}
__device__ __forceinline__ u64 pack2f(float x, float y) {
    u64 r; asm("mov.b64 %0, {%1, %2};" : "=l"(r) : "f"(x), "f"(y)); return r;
}
__device__ __forceinline__ float2 unpack2(u64 a) {
    float2 f; asm("mov.b64 {%0, %1}, %2;" : "=f"(f.x), "=f"(f.y) : "l"(a)); return f;
}
__device__ __forceinline__ void ffma2(u64 &d, u64 a, u64 b) {
    asm("fma.rn.f32x2 %0, %1, %2, %0;" : "+l"(d) : "l"(a), "l"(b));
}
__device__ __forceinline__ u64 fmul2(u64 a, u64 b) {
    u64 d; asm("mul.rn.f32x2 %0, %1, %2;" : "=l"(d) : "l"(a), "l"(b)); return d;
}

// Scratch (allocation-free rule: __device__ globals)
__device__ float g_q[BATCH * NTOK * INNER];
__device__ float g_v[BATCH * NTOK * INNER];
__device__ float g_ao[BATCH * NTOK * INNER];
__device__ float g_norm[BATCH * HEADS * NTOK];

// ---------------------------------------------------------------------------
// SGEMM (f32x2): C[M,N] = A[M,K] @ W[K,N] + bias[N]
// 128x128 tile, BK=8, 256 threads, 8x8 per thread (cols = 4tx..+3 and 64+4tx..+3)
// ---------------------------------------------------------------------------
__global__ __launch_bounds__(256, 2) void sgemm_bias(
    const float* __restrict__ A, const float* __restrict__ W,
    const float* __restrict__ bias, float* __restrict__ C,
    int M, int N, int K)
{
    __shared__ float As[8][128];   // [k][m] transposed
    __shared__ float Bs[8][128];   // [k][n]

    const int tid = threadIdx.x;
    const int bm = blockIdx.y * 128;
    const int bn = blockIdx.x * 128;
    const int tx = tid & 15;
    const int ty = tid >> 4;

    const int arow = tid >> 1;
    const int acol = (tid & 1) * 4;
    const int brow = tid >> 5;
    const int bcol = (tid & 31) * 4;

    const float* Ap = A + (size_t)(bm + arow) * K + acol;
    const float* Wp = W + (size_t)brow * N + bn + bcol;

    u64 acc[8][4];   // [i][j-pair]: pairs 0,1 -> cols 4tx..+3 ; pairs 2,3 -> 64+4tx..+3
    #pragma unroll
    for (int i = 0; i < 8; i++)
        #pragma unroll
        for (int j = 0; j < 4; j++) acc[i][j] = 0ull;

    for (int k0 = 0; k0 < K; k0 += 8) {
        float4 a4 = *(const float4*)(Ap + k0);
        As[acol + 0][arow] = a4.x;
        As[acol + 1][arow] = a4.y;
        As[acol + 2][arow] = a4.z;
        As[acol + 3][arow] = a4.w;
        *(float4*)&Bs[brow][bcol] = *(const float4*)(Wp + (size_t)k0 * N);
        __syncthreads();

        #pragma unroll
        for (int kk = 0; kk < 8; kk++) {
            float4 a0 = *(const float4*)&As[kk][ty * 8];
            float4 a1 = *(const float4*)&As[kk][ty * 8 + 4];
            alignas(16) u64 b2[4];
            *(float4*)&b2[0] = *(const float4*)&Bs[kk][tx * 4];
            *(float4*)&b2[2] = *(const float4*)&Bs[kk][64 + tx * 4];
            u64 ad[8];
            ad[0] = pack2(a0.x); ad[1] = pack2(a0.y);
            ad[2] = pack2(a0.z); ad[3] = pack2(a0.w);
            ad[4] = pack2(a1.x); ad[5] = pack2(a1.y);
            ad[6] = pack2(a1.z); ad[7] = pack2(a1.w);
            #pragma unroll
            for (int i = 0; i < 8; i++)
                #pragma unroll
                for (int j = 0; j < 4; j++)
                    ffma2(acc[i][j], ad[i], b2[j]);
        }
        __syncthreads();
    }

    float4 bb0 = *(const float4*)(bias + bn + tx * 4);
    float4 bb1 = *(const float4*)(bias + bn + 64 + tx * 4);

    #pragma unroll
    for (int i = 0; i < 8; i++) {
        float* Cp = C + (size_t)(bm + ty * 8 + i) * N + bn;
        float2 p0 = unpack2(acc[i][0]), p1 = unpack2(acc[i][1]);
        float2 p2 = unpack2(acc[i][2]), p3 = unpack2(acc[i][3]);
        float4 o0 = make_float4(p0.x + bb0.x, p0.y + bb0.y, p1.x + bb0.z, p1.y + bb0.w);
        float4 o1 = make_float4(p2.x + bb1.x, p2.y + bb1.y, p3.x + bb1.z, p3.y + bb1.w);
        *(float4*)(Cp + tx * 4) = o0;
        *(float4*)(Cp + 64 + tx * 4) = o1;
    }
}

// ---------------------------------------------------------------------------
// Row norms: norms[(b*H + h)*NTOK + n] = sum_d q[b,n,h*64+d]^2
// ---------------------------------------------------------------------------
__global__ __launch_bounds__(256) void compute_norms(
    const float* __restrict__ q, float* __restrict__ norms)
{
    int idx = blockIdx.x * 256 + threadIdx.x;
    int n  = idx & (NTOK - 1);
    int bh = idx >> 11;
    int h = bh & (HEADS - 1);
    int b = bh >> 4;
    const float* p = q + ((size_t)(b * NTOK + n)) * INNER + h * DH;
    float s = 0.f;
    #pragma unroll
    for (int d = 0; d < DH; d += 4) {
        float4 t = *(const float4*)(p + d);
        s += t.x * t.x + t.y * t.y + t.z * t.z + t.w * t.w;
    }
    norms[idx] = s;
}

// ---------------------------------------------------------------------------
// Flash attention (k=q), f32x2.  S_ij = (2*q_i.q_j - |q_j|^2)*SCALE
// i-tile 128, j-tile 64, 256 threads, per-thread 8i x 4j (i in f32x2 pairs).
// ---------------------------------------------------------------------------
#define QSTR 132
#define KSTR 68
#define VSTR 68
#define PSTR 132

__global__ __launch_bounds__(256) void attn_kernel(
    const float* __restrict__ q, const float* __restrict__ v,
    const float* __restrict__ norms, float* __restrict__ ao)
{
    extern __shared__ float sm[];
    float* Qs = sm;                  // [64][QSTR]  (d-major, i contiguous)
    float* Ks = Qs + 64 * QSTR;      // [64][KSTR]  (d-major, j contiguous)
    float* Vs = Ks + 64 * KSTR;      // [64][VSTR]  (j-major, d contiguous)
    float* Ps = Vs + 64 * VSTR;      // [64][PSTR]  (j-major, i contiguous)
    float* kn = Ps + 64 * PSTR;      // [64]

    const int tid = threadIdx.x;
    const int tx = tid & 15;         // j-group
    const int ty = tid >> 4;         // i-group (8 rows)
    const int i0 = blockIdx.x * 128;
    const int bh = blockIdx.y;
    const int h = bh & (HEADS - 1);
    const int b = bh >> 4;

    const float* qb = q + (size_t)b * NTOK * INNER + h * DH;
    const float* vb = v + (size_t)b * NTOK * INNER + h * DH;
    const float* nb = norms + (size_t)bh * NTOK;

    // Q tile transposed: Qs[d][i], 128 rows
    #pragma unroll
    for (int it = 0; it < 8; it++) {
        int idx = tid + it * 256;
        int r = idx >> 4;
        int d = (idx & 15) * 4;
        float4 t = *(const float4*)(qb + (size_t)(i0 + r) * INNER + d);
        Qs[(d + 0) * QSTR + r] = t.x;
        Qs[(d + 1) * QSTR + r] = t.y;
        Qs[(d + 2) * QSTR + r] = t.z;
        Qs[(d + 3) * QSTR + r] = t.w;
    }

    float m[8], l[8], corr[8];
    u64 acco[4][4];                  // [i-pair][c]
    #pragma unroll
    for (int r = 0; r < 8; r++) { m[r] = -1e30f; l[r] = 0.f; }
    #pragma unroll
    for (int ip = 0; ip < 4; ip++)
        #pragma unroll
        for (int c = 0; c < 4; c++) acco[ip][c] = 0ull;

    for (int j0 = 0; j0 < NTOK; j0 += 64) {
        __syncthreads();   // prev-tile smem reads done (also fences Q store)

        // K transposed + V natural + norms
        #pragma unroll
        for (int it = 0; it < 4; it++) {
            int idx = tid + it * 256;
            int r = idx >> 4;
            int d = (idx & 15) * 4;
            float4 kt = *(const float4*)(qb + (size_t)(j0 + r) * INNER + d);
            Ks[(d + 0) * KSTR + r] = kt.x;
            Ks[(d + 1) * KSTR + r] = kt.y;
            Ks[(d + 2) * KSTR + r] = kt.z;
            Ks[(d + 3) * KSTR + r] = kt.w;
            float4 vt = *(const float4*)(vb + (size_t)(j0 + r) * INNER + d);
            *(float4*)&Vs[r * VSTR + d] = vt;
        }
        if (tid < 64) kn[tid] = nb[j0 + tid];
        __syncthreads();

        // ---- S = Q @ K^T, pairs over i ----
        u64 accs[4][4];
        #pragma unroll
        for (int ip = 0; ip < 4; ip++)
            #pragma unroll
            for (int c = 0; c < 4; c++) accs[ip][c] = 0ull;

        #pragma unroll 4
        for (int kk = 0; kk < 64; kk++) {
            alignas(16) u64 a2[4];
            *(float4*)&a2[0] = *(const float4*)&Qs[kk * QSTR + ty * 8];
            *(float4*)&a2[2] = *(const float4*)&Qs[kk * QSTR + ty * 8 + 4];
            float4 kv = *(const float4*)&Ks[kk * KSTR + tx * 4];
            u64 b2[4];
            b2[0] = pack2(kv.x); b2[1] = pack2(kv.y);
            b2[2] = pack2(kv.z); b2[3] = pack2(kv.w);
            #pragma unroll
            for (int ip = 0; ip < 4; ip++)
                #pragma unroll
                for (int c = 0; c < 4; c++)
                    ffma2(accs[ip][c], a2[ip], b2[c]);
        }

        // ---- online softmax ----
        float lk[4];
        #pragma unroll
        for (int c = 0; c < 4; c++) lk[c] = kn[tx * 4 + c];

        float s[8][4];
        #pragma unroll
        for (int ip = 0; ip < 4; ip++)
            #pragma unroll
            for (int c = 0; c < 4; c++) {
                float2 t = unpack2(accs[ip][c]);
                s[2 * ip][c]     = (2.f * t.x - lk[c]) * SCALE;
                s[2 * ip + 1][c] = (2.f * t.y - lk[c]) * SCALE;
            }

        #pragma unroll
        for (int r = 0; r < 8; r++) {
            float mx = fmaxf(fmaxf(s[r][0], s[r][1]), fmaxf(s[r][2], s[r][3]));
            #pragma unroll
            for (int off = 8; off > 0; off >>= 1)
                mx = fmaxf(mx, __shfl_xor_sync(0xffffffffu, mx, off));
            float nm = fmaxf(m[r], mx);
            corr[r] = __expf(m[r] - nm);
            m[r] = nm;
            float rs = 0.f;
            #pragma unroll
            for (int c = 0; c < 4; c++) {
                s[r][c] = __expf(s[r][c] - nm);   // becomes P
                rs += s[r][c];
            }
            #pragma unroll
            for (int off = 8; off > 0; off >>= 1)
                rs += __shfl_xor_sync(0xffffffffu, rs, off);
            l[r] = l[r] * corr[r] + rs;
        }

        #pragma unroll
        for (int ip = 0; ip < 4; ip++) {
            u64 cp = pack2f(corr[2 * ip], corr[2 * ip + 1]);
            #pragma unroll
            for (int c = 0; c < 4; c++) acco[ip][c] = fmul2(acco[ip][c], cp);
        }

        // store P (j-major, i contiguous)
        #pragma unroll
        for (int c = 0; c < 4; c++) {
            int j = tx * 4 + c;
            float4 p0 = make_float4(s[0][c], s[1][c], s[2][c], s[3][c]);
            float4 p1 = make_float4(s[4][c], s[5][c], s[6][c], s[7][c]);
            *(float4*)&Ps[j * PSTR + ty * 8] = p0;
            *(float4*)&Ps[j * PSTR + ty * 8 + 4] = p1;
        }
        __syncthreads();

        // ---- acco += P @ V, pairs over i ----
        #pragma unroll 2
        for (int j = 0; j < 64; j++) {
            alignas(16) u64 p2[4];
            *(float4*)&p2[0] = *(const float4*)&Ps[j * PSTR + ty * 8];
            *(float4*)&p2[2] = *(const float4*)&Ps[j * PSTR + ty * 8 + 4];
            float4 vv = *(const float4*)&Vs[j * VSTR + tx * 4];
            u64 v2[4];
            v2[0] = pack2(vv.x); v2[1] = pack2(vv.y);
            v2[2] = pack2(vv.z); v2[3] = pack2(vv.w);
            #pragma unroll
            for (int ip = 0; ip < 4; ip++)
                #pragma unroll
                for (int c = 0; c < 4; c++)
                    ffma2(acco[ip][c], p2[ip], v2[c]);
        }
    }

    // epilogue
    float* ob = ao + ((size_t)b * NTOK + i0) * INNER + h * DH;
    #pragma unroll
    for (int ip = 0; ip < 4; ip++) {
        float2 o0 = unpack2(acco[ip][0]);
        float2 o1 = unpack2(acco[ip][1]);
        float2 o2 = unpack2(acco[ip][2]);
        float2 o3 = unpack2(acco[ip][3]);
        int r0 = ty * 8 + 2 * ip;
        float inv0 = 1.f / l[2 * ip];
        float inv1 = 1.f / l[2 * ip + 1];
        float4 w0 = make_float4(o0.x * inv0, o1.x * inv0, o2.x * inv0, o3.x * inv0);
        float4 w1 = make_float4(o0.y * inv1, o1.y * inv1, o2.y * inv1, o3.y * inv1);
        *(float4*)(ob + (size_t)r0 * INNER + tx * 4) = w0;
        *(float4*)(ob + (size_t)(r0 + 1) * INNER + tx * 4) = w1;
    }
}

// ---------------------------------------------------------------------------
extern "C" void kernel_launch(void* const* d_in, const int* in_sizes, int n_in,
                              void* d_out, int out_size)
{
    const float* x  = (const float*)d_in[0];
    const float* Wq = (const float*)d_in[1];
    const float* bq = (const float*)d_in[2];
    const float* Wv = (const float*)d_in[3];
    const float* bv = (const float*)d_in[4];
    const float* Wo = (const float*)d_in[5];
    const float* bo = (const float*)d_in[6];
    float* out = (float*)d_out;

    float *qp, *vp, *aop, *np;
    cudaGetSymbolAddress((void**)&qp,  g_q);
    cudaGetSymbolAddress((void**)&vp,  g_v);
    cudaGetSymbolAddress((void**)&aop, g_ao);
    cudaGetSymbolAddress((void**)&np,  g_norm);

    const int M = BATCH * NTOK;   // 8192

    dim3 ggp(INNER / 128, M / 128);
    sgemm_bias<<<ggp, 256>>>(x, Wq, bq, qp, M, INNER, DMODEL);
    sgemm_bias<<<ggp, 256>>>(x, Wv, bv, vp, M, INNER, DMODEL);

    compute_norms<<<(BATCH * HEADS * NTOK) / 256, 256>>>(qp, np);

    int smem = (64 * QSTR + 64 * KSTR + 64 * VSTR + 64 * PSTR + 64) * (int)sizeof(float);
    cudaFuncSetAttribute(attn_kernel,
                         cudaFuncAttributeMaxDynamicSharedMemorySize, smem);
    attn_kernel<<<dim3(NTOK / 128, BATCH * HEADS), 256, smem>>>(qp, vp, np, aop);

    sgemm_bias<<<dim3(DMODEL / 128, M / 128), 256>>>(aop, Wo, bo, out, M, DMODEL, INNER);
}

// round 6
// speedup vs baseline: 1.0006x; 1.0006x over previous
#include <cuda_runtime.h>
#include <math.h>

#define BATCH 4
#define NTOK  2048
#define DMODEL 1024
#define HEADS 16
#define DH    64
#define INNER 1024
#define SCALE 0.125f   /* 64^-0.5 */

typedef unsigned long long u64;

__device__ __forceinline__ u64 pack2(float x) {
    u64 r; asm("mov.b64 %0, {%1, %1};" : "=l"(r) : "f"(x)); return r;
}
__device__ __forceinline__ u64 pack2f(float x, float y) {
    u64 r; asm("mov.b64 %0, {%1, %2};" : "=l"(r) : "f"(x), "f"(y)); return r;
}
__device__ __forceinline__ float2 unpack2(u64 a) {
    float2 f; asm("mov.b64 {%0, %1}, %2;" : "=f"(f.x), "=f"(f.y) : "l"(a)); return f;
}
__device__ __forceinline__ void ffma2(u64 &d, u64 a, u64 b) {
    asm("fma.rn.f32x2 %0, %1, %2, %0;" : "+l"(d) : "l"(a), "l"(b));
}
__device__ __forceinline__ u64 fmul2(u64 a, u64 b) {
    u64 d; asm("mul.rn.f32x2 %0, %1, %2;" : "=l"(d) : "l"(a), "l"(b)); return d;
}

// Scratch (allocation-free rule: __device__ globals)
__device__ float g_q[BATCH * NTOK * INNER];
__device__ float g_v[BATCH * NTOK * INNER];
__device__ float g_ao[BATCH * NTOK * INNER];
__device__ float g_norm[BATCH * HEADS * NTOK];

// ---------------------------------------------------------------------------
// SGEMM (f32x2): C[M,N] = A[M,K] @ W[K,N] + bias[N]
// 128x128 tile, BK=8, 256 threads, 8x8 per thread (cols = 4tx..+3 and 64+4tx..+3)
// ---------------------------------------------------------------------------
__global__ __launch_bounds__(256, 2) void sgemm_bias(
    const float* __restrict__ A, const float* __restrict__ W,
    const float* __restrict__ bias, float* __restrict__ C,
    int M, int N, int K)
{
    __shared__ float As[8][128];   // [k][m] transposed
    __shared__ float Bs[8][128];   // [k][n]

    const int tid = threadIdx.x;
    const int bm = blockIdx.y * 128;
    const int bn = blockIdx.x * 128;
    const int tx = tid & 15;
    const int ty = tid >> 4;

    const int arow = tid >> 1;
    const int acol = (tid & 1) * 4;
    const int brow = tid >> 5;
    const int bcol = (tid & 31) * 4;

    const float* Ap = A + (size_t)(bm + arow) * K + acol;
    const float* Wp = W + (size_t)brow * N + bn + bcol;

    u64 acc[8][4];   // [i][j-pair]: pairs 0,1 -> cols 4tx..+3 ; pairs 2,3 -> 64+4tx..+3
    #pragma unroll
    for (int i = 0; i < 8; i++)
        #pragma unroll
        for (int j = 0; j < 4; j++) acc[i][j] = 0ull;

    for (int k0 = 0; k0 < K; k0 += 8) {
        float4 a4 = *(const float4*)(Ap + k0);
        As[acol + 0][arow] = a4.x;
        As[acol + 1][arow] = a4.y;
        As[acol + 2][arow] = a4.z;
        As[acol + 3][arow] = a4.w;
        *(float4*)&Bs[brow][bcol] = *(const float4*)(Wp + (size_t)k0 * N);
        __syncthreads();

        #pragma unroll
        for (int kk = 0; kk < 8; kk++) {
            float4 a0 = *(const float4*)&As[kk][ty * 8];
            float4 a1 = *(const float4*)&As[kk][ty * 8 + 4];
            alignas(16) u64 b2[4];
            *(float4*)&b2[0] = *(const float4*)&Bs[kk][tx * 4];
            *(float4*)&b2[2] = *(const float4*)&Bs[kk][64 + tx * 4];
            u64 ad[8];
            ad[0] = pack2(a0.x); ad[1] = pack2(a0.y);
            ad[2] = pack2(a0.z); ad[3] = pack2(a0.w);
            ad[4] = pack2(a1.x); ad[5] = pack2(a1.y);
            ad[6] = pack2(a1.z); ad[7] = pack2(a1.w);
            #pragma unroll
            for (int i = 0; i < 8; i++)
                #pragma unroll
                for (int j = 0; j < 4; j++)
                    ffma2(acc[i][j], ad[i], b2[j]);
        }
        __syncthreads();
    }

    float4 bb0 = *(const float4*)(bias + bn + tx * 4);
    float4 bb1 = *(const float4*)(bias + bn + 64 + tx * 4);

    #pragma unroll
    for (int i = 0; i < 8; i++) {
        float* Cp = C + (size_t)(bm + ty * 8 + i) * N + bn;
        float2 p0 = unpack2(acc[i][0]), p1 = unpack2(acc[i][1]);
        float2 p2 = unpack2(acc[i][2]), p3 = unpack2(acc[i][3]);
        float4 o0 = make_float4(p0.x + bb0.x, p0.y + bb0.y, p1.x + bb0.z, p1.y + bb0.w);
        float4 o1 = make_float4(p2.x + bb1.x, p2.y + bb1.y, p3.x + bb1.z, p3.y + bb1.w);
        *(float4*)(Cp + tx * 4) = o0;
        *(float4*)(Cp + 64 + tx * 4) = o1;
    }
}

// ---------------------------------------------------------------------------
// Row norms: norms[(b*H + h)*NTOK + n] = sum_d q[b,n,h*64+d]^2
// ---------------------------------------------------------------------------
__global__ __launch_bounds__(256) void compute_norms(
    const float* __restrict__ q, float* __restrict__ norms)
{
    int idx = blockIdx.x * 256 + threadIdx.x;
    int n  = idx & (NTOK - 1);
    int bh = idx >> 11;
    int h = bh & (HEADS - 1);
    int b = bh >> 4;
    const float* p = q + ((size_t)(b * NTOK + n)) * INNER + h * DH;
    float s = 0.f;
    #pragma unroll
    for (int d = 0; d < DH; d += 4) {
        float4 t = *(const float4*)(p + d);
        s += t.x * t.x + t.y * t.y + t.z * t.z + t.w * t.w;
    }
    norms[idx] = s;
}

// ---------------------------------------------------------------------------
// Flash attention (k=q), f32x2.  S_ij = (2*q_i.q_j - |q_j|^2)*SCALE
// i-tile 128, j-tile 64, 256 threads, per-thread 8i x 4j (i in f32x2 pairs).
// ---------------------------------------------------------------------------
#define QSTR 132
#define KSTR 68
#define VSTR 68
#define PSTR 132

__global__ __launch_bounds__(256) void attn_kernel(
    const float* __restrict__ q, const float* __restrict__ v,
    const float* __restrict__ norms, float* __restrict__ ao)
{
    extern __shared__ float sm[];
    float* Qs = sm;                  // [64][QSTR]  (d-major, i contiguous)
    float* Ks = Qs + 64 * QSTR;      // [64][KSTR]  (d-major, j contiguous)
    float* Vs = Ks + 64 * KSTR;      // [64][VSTR]  (j-major, d contiguous)
    float* Ps = Vs + 64 * VSTR;      // [64][PSTR]  (j-major, i contiguous)
    float* kn = Ps + 64 * PSTR;      // [64]

    const int tid = threadIdx.x;
    const int tx = tid & 15;         // j-group
    const int ty = tid >> 4;         // i-group (8 rows)
    const int i0 = blockIdx.x * 128;
    const int bh = blockIdx.y;
    const int h = bh & (HEADS - 1);
    const int b = bh >> 4;

    const float* qb = q + (size_t)b * NTOK * INNER + h * DH;
    const float* vb = v + (size_t)b * NTOK * INNER + h * DH;
    const float* nb = norms + (size_t)bh * NTOK;

    // Q tile transposed: Qs[d][i], 128 rows
    #pragma unroll
    for (int it = 0; it < 8; it++) {
        int idx = tid + it * 256;
        int r = idx >> 4;
        int d = (idx & 15) * 4;
        float4 t = *(const float4*)(qb + (size_t)(i0 + r) * INNER + d);
        Qs[(d + 0) * QSTR + r] = t.x;
        Qs[(d + 1) * QSTR + r] = t.y;
        Qs[(d + 2) * QSTR + r] = t.z;
        Qs[(d + 3) * QSTR + r] = t.w;
    }

    float m[8], l[8], corr[8];
    u64 acco[4][4];                  // [i-pair][c]
    #pragma unroll
    for (int r = 0; r < 8; r++) { m[r] = -1e30f; l[r] = 0.f; }
    #pragma unroll
    for (int ip = 0; ip < 4; ip++)
        #pragma unroll
        for (int c = 0; c < 4; c++) acco[ip][c] = 0ull;

    for (int j0 = 0; j0 < NTOK; j0 += 64) {
        __syncthreads();   // prev-tile smem reads done (also fences Q store)

        // K transposed + V natural + norms
        #pragma unroll
        for (int it = 0; it < 4; it++) {
            int idx = tid + it * 256;
            int r = idx >> 4;
            int d = (idx & 15) * 4;
            float4 kt = *(const float4*)(qb + (size_t)(j0 + r) * INNER + d);
            Ks[(d + 0) * KSTR + r] = kt.x;
            Ks[(d + 1) * KSTR + r] = kt.y;
            Ks[(d + 2) * KSTR + r] = kt.z;
            Ks[(d + 3) * KSTR + r] = kt.w;
            float4 vt = *(const float4*)(vb + (size_t)(j0 + r) * INNER + d);
            *(float4*)&Vs[r * VSTR + d] = vt;
        }
        if (tid < 64) kn[tid] = nb[j0 + tid];
        __syncthreads();

        // ---- S = Q @ K^T, pairs over i ----
        u64 accs[4][4];
        #pragma unroll
        for (int ip = 0; ip < 4; ip++)
            #pragma unroll
            for (int c = 0; c < 4; c++) accs[ip][c] = 0ull;

        #pragma unroll 4
        for (int kk = 0; kk < 64; kk++) {
            alignas(16) u64 a2[4];
            *(float4*)&a2[0] = *(const float4*)&Qs[kk * QSTR + ty * 8];
            *(float4*)&a2[2] = *(const float4*)&Qs[kk * QSTR + ty * 8 + 4];
            float4 kv = *(const float4*)&Ks[kk * KSTR + tx * 4];
            u64 b2[4];
            b2[0] = pack2(kv.x); b2[1] = pack2(kv.y);
            b2[2] = pack2(kv.z); b2[3] = pack2(kv.w);
            #pragma unroll
            for (int ip = 0; ip < 4; ip++)
                #pragma unroll
                for (int c = 0; c < 4; c++)
                    ffma2(accs[ip][c], a2[ip], b2[c]);
        }

        // ---- online softmax ----
        float lk[4];
        #pragma unroll
        for (int c = 0; c < 4; c++) lk[c] = kn[tx * 4 + c];

        float s[8][4];
        #pragma unroll
        for (int ip = 0; ip < 4; ip++)
            #pragma unroll
            for (int c = 0; c < 4; c++) {
                float2 t = unpack2(accs[ip][c]);
                s[2 * ip][c]     = (2.f * t.x - lk[c]) * SCALE;
                s[2 * ip + 1][c] = (2.f * t.y - lk[c]) * SCALE;
            }

        #pragma unroll
        for (int r = 0; r < 8; r++) {
            float mx = fmaxf(fmaxf(s[r][0], s[r][1]), fmaxf(s[r][2], s[r][3]));
            #pragma unroll
            for (int off = 8; off > 0; off >>= 1)
                mx = fmaxf(mx, __shfl_xor_sync(0xffffffffu, mx, off));
            float nm = fmaxf(m[r], mx);
            corr[r] = __expf(m[r] - nm);
            m[r] = nm;
            float rs = 0.f;
            #pragma unroll
            for (int c = 0; c < 4; c++) {
                s[r][c] = __expf(s[r][c] - nm);   // becomes P
                rs += s[r][c];
            }
            #pragma unroll
            for (int off = 8; off > 0; off >>= 1)
                rs += __shfl_xor_sync(0xffffffffu, rs, off);
            l[r] = l[r] * corr[r] + rs;
        }

        #pragma unroll
        for (int ip = 0; ip < 4; ip++) {
            u64 cp = pack2f(corr[2 * ip], corr[2 * ip + 1]);
            #pragma unroll
            for (int c = 0; c < 4; c++) acco[ip][c] = fmul2(acco[ip][c], cp);
        }

        // store P (j-major, i contiguous)
        #pragma unroll
        for (int c = 0; c < 4; c++) {
            int j = tx * 4 + c;
            float4 p0 = make_float4(s[0][c], s[1][c], s[2][c], s[3][c]);
            float4 p1 = make_float4(s[4][c], s[5][c], s[6][c], s[7][c]);
            *(float4*)&Ps[j * PSTR + ty * 8] = p0;
            *(float4*)&Ps[j * PSTR + ty * 8 + 4] = p1;
        }
        __syncthreads();

        // ---- acco += P @ V, pairs over i ----
        #pragma unroll 2
        for (int j = 0; j < 64; j++) {
            alignas(16) u64 p2[4];
            *(float4*)&p2[0] = *(const float4*)&Ps[j * PSTR + ty * 8];
            *(float4*)&p2[2] = *(const float4*)&Ps[j * PSTR + ty * 8 + 4];
            float4 vv = *(const float4*)&Vs[j * VSTR + tx * 4];
            u64 v2[4];
            v2[0] = pack2(vv.x); v2[1] = pack2(vv.y);
            v2[2] = pack2(vv.z); v2[3] = pack2(vv.w);
            #pragma unroll
            for (int ip = 0; ip < 4; ip++)
                #pragma unroll
                for (int c = 0; c < 4; c++)
                    ffma2(acco[ip][c], p2[ip], v2[c]);
        }
    }

    // epilogue
    float* ob = ao + ((size_t)b * NTOK + i0) * INNER + h * DH;
    #pragma unroll
    for (int ip = 0; ip < 4; ip++) {
        float2 o0 = unpack2(acco[ip][0]);
        float2 o1 = unpack2(acco[ip][1]);
        float2 o2 = unpack2(acco[ip][2]);
        float2 o3 = unpack2(acco[ip][3]);
        int r0 = ty * 8 + 2 * ip;
        float inv0 = 1.f / l[2 * ip];
        float inv1 = 1.f / l[2 * ip + 1];
        float4 w0 = make_float4(o0.x * inv0, o1.x * inv0, o2.x * inv0, o3.x * inv0);
        float4 w1 = make_float4(o0.y * inv1, o1.y * inv1, o2.y * inv1, o3.y * inv1);
        *(float4*)(ob + (size_t)r0 * INNER + tx * 4) = w0;
        *(float4*)(ob + (size_t)(r0 + 1) * INNER + tx * 4) = w1;
    }
}

// ---------------------------------------------------------------------------
extern "C" void kernel_launch(void* const* d_in, const int* in_sizes, int n_in,
                              void* d_out, int out_size)
{
    const float* x  = (const float*)d_in[0];
    const float* Wq = (const float*)d_in[1];
    const float* bq = (const float*)d_in[2];
    const float* Wv = (const float*)d_in[3];
    const float* bv = (const float*)d_in[4];
    const float* Wo = (const float*)d_in[5];
    const float* bo = (const float*)d_in[6];
    float* out = (float*)d_out;

    float *qp, *vp, *aop, *np;
    cudaGetSymbolAddress((void**)&qp,  g_q);
    cudaGetSymbolAddress((void**)&vp,  g_v);
    cudaGetSymbolAddress((void**)&aop, g_ao);
    cudaGetSymbolAddress((void**)&np,  g_norm);

    const int M = BATCH * NTOK;   // 8192

    dim3 ggp(INNER / 128, M / 128);
    sgemm_bias<<<ggp, 256>>>(x, Wq, bq, qp, M, INNER, DMODEL);
    sgemm_bias<<<ggp, 256>>>(x, Wv, bv, vp, M, INNER, DMODEL);

    compute_norms<<<(BATCH * HEADS * NTOK) / 256, 256>>>(qp, np);

    int smem = (64 * QSTR + 64 * KSTR + 64 * VSTR + 64 * PSTR + 64) * (int)sizeof(float);
    cudaFuncSetAttribute(attn_kernel,
                         cudaFuncAttributeMaxDynamicSharedMemorySize, smem);
    attn_kernel<<<dim3(NTOK / 128, BATCH * HEADS), 256, smem>>>(qp, vp, np, aop);

    sgemm_bias<<<dim3(DMODEL / 128, M / 128), 256>>>(aop, Wo, bo, out, M, DMODEL, INNER);
}